// round 1
// baseline (speedup 1.0000x reference)
#include <cuda_runtime.h>

// CYK inside algorithm (TreeCRF partition). B=128 batches, L=256.
// One CTA per batch; whole triangular DP table in shared memory.
// Diagonal-major packed layout: row w (span width) has L-w entries at
// off(w) = w*L - w*(w-1)/2.  Cell (w,i) == I(i, i+w).
// Recurrence: I(w,i) = span(w,i) + logsumexp_{k=1..w-1}( d[k][i] + d[w-k][i+k] )

constexpr int SL  = 256;                 // sequence length L
constexpr int NB  = 128;                 // batches
constexpr int NT  = 512;                 // threads per CTA
constexpr int TRI = (SL * (SL + 1)) / 2; // 32896 floats = 131584 bytes
constexpr float NEGF = -1000000000.0f;

__global__ __launch_bounds__(NT, 1)
void cyk_kernel(const float* __restrict__ s_span,
                const int* __restrict__ lens,
                float* __restrict__ out)
{
    extern __shared__ float sd[];
    const int tid = threadIdx.x;
    const int b = blockIdx.x;
    const float* S = s_span + (long long)b * (SL * SL);

    // init whole table to NEG (covers row 0 and all never-written cells)
    for (int idx = tid; idx < TRI; idx += NT) sd[idx] = NEGF;
    __syncthreads();
    // row w=1: d[1][i] = s_span[b,i,i+1] for i < L-1
    for (int i = tid; i < SL - 1; i += NT) sd[SL + i] = S[i * (SL + 1) + 1];
    __syncthreads();

    int offw = 2 * SL - 1; // off(2)
    for (int w = 2; w < SL; ++w) {
        const int ncell = SL - w;

        // group size G = largest pow2 with ncell*G <= NT, capped at 32
        int lg = 0;
        while (lg < 5 && (ncell << (lg + 1)) <= NT) ++lg;
        const int G = 1 << lg;
        const int cell = tid >> lg;      // which i this group handles
        const int g = tid & (G - 1);     // lane within group
        const int i = min(cell, ncell - 1); // clamp so all loads stay in-bounds

        // prefetch span score early (latency hidden behind the k-loop)
        const float sp = S[i * (SL + 1) + w];

        // Two independent accumulator chains per thread, each stride St = 2G,
        // to break the loop-carried sub->exp->fma dependency chain.
        const int St = G << 1;
        const int StSq = St * St;
        const int hSt = (St * (St - 1)) >> 1;
        const int kA = 1 + g;
        const int kB = kA + G;
        const int cA = (kA <= w - 1) ? (((w - 1 - kA) >> (lg + 1)) + 1) : 0;
        const int cB = (kB <= w - 1) ? (((w - 1 - kB) >> (lg + 1)) + 1) : 0;

        // left  addr: a(k) = k*L - k(k-1)/2 + i,  delta(k) = St*L - k*St - hSt,  delta' = delta - St^2
        // right addr: r=w-k; a = r*L - r(r-1)/2 + i + k, delta = r*St - St*L - hSt, delta' = delta - St^2
        int aAl = kA * SL - ((kA * (kA - 1)) >> 1) + i;
        int dAl = St * SL - kA * St - hSt;
        const int rA = w - kA;
        int aAr = rA * SL - ((rA * (rA - 1)) >> 1) + i + kA;
        int dAr = rA * St - St * SL - hSt;

        int aBl = kB * SL - ((kB * (kB - 1)) >> 1) + i;
        int dBl = St * SL - kB * St - hSt;
        const int rB = w - kB;
        int aBr = rB * SL - ((rB * (rB - 1)) >> 1) + i + kB;
        int dBr = rB * St - St * SL - hSt;

        float mA = NEGF, sA = 0.f, mB = NEGF, sB = 0.f;

        // Online logsumexp with a single exp per element:
        //   d = v - m;  t = exp(-|d|);
        //   if d>0:  s = s*t + 1, m = v   else  s = s + t
        for (int n = 0; n < cB; ++n) {
            {
                const float v = sd[aAl] + sd[aAr];
                const float d = v - mA;
                const float t = __expf(-fabsf(d));
                sA = (d > 0.f) ? (sA * t + 1.f) : (sA + t);
                mA = fmaxf(mA, v);
                aAl += dAl; dAl -= StSq; aAr += dAr; dAr -= StSq;
            }
            {
                const float v = sd[aBl] + sd[aBr];
                const float d = v - mB;
                const float t = __expf(-fabsf(d));
                sB = (d > 0.f) ? (sB * t + 1.f) : (sB + t);
                mB = fmaxf(mB, v);
                aBl += dBl; dBl -= StSq; aBr += dBr; dBr -= StSq;
            }
        }
        if (cA > cB) { // chain A may have one extra element
            const float v = sd[aAl] + sd[aAr];
            const float d = v - mA;
            const float t = __expf(-fabsf(d));
            sA = (d > 0.f) ? (sA * t + 1.f) : (sA + t);
            mA = fmaxf(mA, v);
        }

        // merge the two chains (NEGF-safe: exp(NEGF - finite) underflows to 0,
        // exp(NEGF-NEGF)=1 pairs with s=0)
        float m = fmaxf(mA, mB);
        float s = sA * __expf(mA - m) + sB * __expf(mB - m);

        // warp-shuffle logsumexp reduction across the G lanes of the group.
        // All threads participate (groups are pow2-aligned within warps).
        for (int o = G >> 1; o > 0; o >>= 1) {
            const float mo = __shfl_xor_sync(0xffffffffu, m, o);
            const float so = __shfl_xor_sync(0xffffffffu, s, o);
            const float M2 = fmaxf(m, mo);
            s = s * __expf(m - M2) + so * __expf(mo - M2);
            m = M2;
        }

        if (g == 0 && cell < ncell) {
            sd[offw + cell] = m + __logf(s) + sp;
        }
        offw += ncell; // off(w+1) = off(w) + (L - w)
        __syncthreads();
    }

    if (tid == 0) {
        const int len = lens[b];
        const int o = len * SL - ((len * (len - 1)) >> 1);
        out[b] = sd[o];
    }
}

extern "C" void kernel_launch(void* const* d_in, const int* in_sizes, int n_in,
                              void* d_out, int out_size)
{
    const float* s_span = (const float*)d_in[0];
    const int* lens = (const int*)d_in[1];
    float* out = (float*)d_out;
    cudaFuncSetAttribute(cyk_kernel, cudaFuncAttributeMaxDynamicSharedMemorySize,
                         TRI * (int)sizeof(float));
    cyk_kernel<<<NB, NT, TRI * sizeof(float)>>>(s_span, lens, out);
}

// round 4
// speedup vs baseline: 1.0956x; 1.0956x over previous
#include <cuda_runtime.h>

// CYK inside algorithm (TreeCRF partition). B=128, L=256.
// One CTA per batch; triangular DP table in smem, diagonal-major with rows
// padded to 4-float alignment so LEFT operand loads are float4.
// Recurrence: I(w,i) = span(w,i) + logsumexp_{k=1..w-1}( d[k][i] + d[w-k][i+k] )

constexpr int SL = 256;
constexpr int NB = 128;
constexpr int NT = 512;     // 16 warps
constexpr int NW = 16;
constexpr float NEGF = -1000000000.0f;

// Rows padded to multiple-of-4 floats. In groups of 4 rows (k = 4q..4q+3)
// every row occupies (256 - 4q) floats.
// off(k) = 1024q - 8q(q-1) + m*(256-4q), q=k>>2, m=k&3.
__device__ __forceinline__ int off_row(int k) {
    int q = k >> 2, m = k & 3;
    return 1024 * q - 8 * q * (q - 1) + m * (256 - 4 * q);
}

constexpr int TAB_F   = 33280 + 32;              // off(256)=33280 + slop pad
constexpr int OFF_I   = TAB_F;                   // int off[257] lives here
constexpr int SCRM_F  = 33572;                   // scratch m: [64][17] float4
constexpr int SCRS_F  = SCRM_F + 64 * 17 * 4;    // scratch s: [64][17] float4
constexpr int SMEM_F  = SCRS_F + 64 * 17 * 4;    // total floats
constexpr int SMEM_B  = SMEM_F * 4;              // 169104 bytes

// merge accumulator (m,s) with partial (mo,so):  exact logsumexp combine
__device__ __forceinline__ void lse_merge(float& m, float& s, float mo, float so) {
    float t = __expf(-fabsf(m - mo));
    bool  p = (m >= mo);
    float shi = p ? s : so;
    float slo = p ? so : s;
    s = fmaf(slo, t, shi);
    m = p ? m : mo;
}
// combine two fresh values (one exp) then merge into (m,s)
__device__ __forceinline__ void lse_leaf2(float& m, float& s, float v1, float v2) {
    float mp  = fmaxf(v1, v2);
    float sp2 = 1.0f + __expf(-fabsf(v1 - v2));
    lse_merge(m, s, mp, sp2);
}
// online single-value update
__device__ __forceinline__ void lse_online(float& m, float& s, float v) {
    float d = v - m;
    float t = __expf(-fabsf(d));
    bool  p = (d > 0.0f);
    float a = p ? t : 1.0f;
    float b = p ? 1.0f : t;
    s = fmaf(s, a, b);
    m = p ? v : m;
}

__global__ __launch_bounds__(NT, 1)
void cyk_kernel(const float* __restrict__ s_span,
                const int* __restrict__ lens,
                float* __restrict__ out)
{
    extern __shared__ float sd[];
    int* offs = (int*)(sd + OFF_I);
    const int tid  = threadIdx.x;
    const int ws   = tid >> 5;
    const int lane = tid & 31;
    const int b    = blockIdx.x;
    const float* S = s_span + (long long)b * (SL * SL);

    // init table (+ pad) to NEG; build offset table
    for (int i = tid; i < TAB_F; i += NT) sd[i] = NEGF;
    if (tid <= 256) offs[tid] = off_row(tid);
    __syncthreads();
    // row w=1
    for (int i = tid; i < SL - 1; i += NT) sd[256 + i] = S[i * 257 + 1];
    __syncthreads();

    for (int w = 2; w < SL; ++w) {
        const int ncell = SL - w;
        const int Q = (ncell + 3) >> 2;
        const int wm1 = w - 1;

        // prefetch span score for the reduction phase (latency hidden by k-loop)
        float sp = 0.0f;
        if (tid < ncell) sp = S[tid * 257 + w];

        if (Q >= 16) {
            // ---- Regime A: warp = k-slice (k ≡ ws+1 mod 16), lanes = cell quads
            for (int q = lane; q < Q; q += 32) {
                const int c0 = q << 2;
                float4 m = {NEGF, NEGF, NEGF, NEGF};
                float4 s = {0.f, 0.f, 0.f, 0.f};
                int k = ws + 1;
                for (; k + 16 <= wm1; k += 32) {
                    const int o1 = offs[k]      + c0;
                    const int o2 = offs[k + 16] + c0;
                    const int r1 = offs[w - k]      + c0 + k;
                    const int r2 = offs[w - k - 16] + c0 + k + 16;
                    const float4 L1 = *(const float4*)(sd + o1);
                    const float4 L2 = *(const float4*)(sd + o2);
                    const float a0 = sd[r1], a1 = sd[r1 + 1], a2 = sd[r1 + 2], a3 = sd[r1 + 3];
                    const float b0 = sd[r2], b1 = sd[r2 + 1], b2 = sd[r2 + 2], b3 = sd[r2 + 3];
                    lse_leaf2(m.x, s.x, L1.x + a0, L2.x + b0);
                    lse_leaf2(m.y, s.y, L1.y + a1, L2.y + b1);
                    lse_leaf2(m.z, s.z, L1.z + a2, L2.z + b2);
                    lse_leaf2(m.w, s.w, L1.w + a3, L2.w + b3);
                }
                if (k <= wm1) {
                    const int o1 = offs[k] + c0;
                    const int r1 = offs[w - k] + c0 + k;
                    const float4 L1 = *(const float4*)(sd + o1);
                    lse_online(m.x, s.x, L1.x + sd[r1]);
                    lse_online(m.y, s.y, L1.y + sd[r1 + 1]);
                    lse_online(m.z, s.z, L1.z + sd[r1 + 2]);
                    lse_online(m.w, s.w, L1.w + sd[r1 + 3]);
                }
                *(float4*)(sd + SCRM_F + (q * 17 + ws) * 4) = m;
                *(float4*)(sd + SCRS_F + (q * 17 + ws) * 4) = s;
            }
        } else {
            // ---- Regime B: few cells — lanes jointly split (quad, k-slice)
            int lg = 0;
            while ((1 << lg) < Q) ++lg;          // Qp = 1<<lg, lg <= 4
            const int Qp = 1 << lg;
            int q = lane & (Qp - 1);
            if (q >= Q) q = Q - 1;               // benign duplicate
            const int c0 = q << 2;
            const int nsub = 32 >> lg;
            const int G = nsub << 4;             // total k-slices
            int k = 1 + (lane >> lg) + nsub * ws;
            float4 m = {NEGF, NEGF, NEGF, NEGF};
            float4 s = {0.f, 0.f, 0.f, 0.f};
            for (; k <= wm1; k += G) {
                const int o = offs[k] + c0;
                const int r = offs[w - k] + c0 + k;
                const float4 L = *(const float4*)(sd + o);
                lse_online(m.x, s.x, L.x + sd[r]);
                lse_online(m.y, s.y, L.y + sd[r + 1]);
                lse_online(m.z, s.z, L.z + sd[r + 2]);
                lse_online(m.w, s.w, L.w + sd[r + 3]);
            }
            // shuffle tree over k-sub lanes (same quad bits)
            for (int o = Qp; o < 32; o <<= 1) {
                float mo, so;
                mo = __shfl_xor_sync(0xffffffffu, m.x, o);
                so = __shfl_xor_sync(0xffffffffu, s.x, o);
                lse_merge(m.x, s.x, mo, so);
                mo = __shfl_xor_sync(0xffffffffu, m.y, o);
                so = __shfl_xor_sync(0xffffffffu, s.y, o);
                lse_merge(m.y, s.y, mo, so);
                mo = __shfl_xor_sync(0xffffffffu, m.z, o);
                so = __shfl_xor_sync(0xffffffffu, s.z, o);
                lse_merge(m.z, s.z, mo, so);
                mo = __shfl_xor_sync(0xffffffffu, m.w, o);
                so = __shfl_xor_sync(0xffffffffu, s.w, o);
                lse_merge(m.w, s.w, mo, so);
            }
            if ((lane >> lg) == 0) {
                *(float4*)(sd + SCRM_F + (q * 17 + ws) * 4) = m;
                *(float4*)(sd + SCRS_F + (q * 17 + ws) * 4) = s;
            }
        }
        __syncthreads();

        // ---- per-cell reduction over the 16 warp partials, then write row w.
        // Max-tree (depth 4) + 16 INDEPENDENT exps + 2 fma chains — replaces
        // the serial 15-deep lse_merge chain (~375 cyc tail -> ~80 cyc).
        if (tid < ncell) {
            const int q = tid >> 2, c = tid & 3;
            const int base = (q * 17) * 4 + c;
            float mv[NW], sv[NW];
            #pragma unroll
            for (int w2 = 0; w2 < NW; ++w2) {
                mv[w2] = sd[SCRM_F + base + w2 * 4];
                sv[w2] = sd[SCRS_F + base + w2 * 4];
            }
            float M = mv[0];
            #pragma unroll
            for (int w2 = 1; w2 < NW; ++w2) M = fmaxf(M, mv[w2]);
            float sa = 0.f, sb = 0.f;
            #pragma unroll
            for (int w2 = 0; w2 < NW; w2 += 2) {
                sa = fmaf(sv[w2],     __expf(mv[w2]     - M), sa);
                sb = fmaf(sv[w2 + 1], __expf(mv[w2 + 1] - M), sb);
            }
            sd[offs[w] + tid] = M + __logf(sa + sb) + sp;
        }
        __syncthreads();
    }

    if (tid == 0) {
        out[b] = sd[offs[lens[b]]];
    }
}

extern "C" void kernel_launch(void* const* d_in, const int* in_sizes, int n_in,
                              void* d_out, int out_size)
{
    const float* s_span = (const float*)d_in[0];
    const int* lens = (const int*)d_in[1];
    float* out = (float*)d_out;
    cudaFuncSetAttribute(cyk_kernel, cudaFuncAttributeMaxDynamicSharedMemorySize, SMEM_B);
    cyk_kernel<<<NB, NT, SMEM_B>>>(s_span, lens, out);
}

// round 12
// speedup vs baseline: 1.3809x; 1.2604x over previous
#include <cuda_runtime.h>

// CYK inside algorithm (TreeCRF partition). B=128, L=256.
// One CTA per batch; triangular DP table in smem, diagonal-major.
// Recurrence: I(w,i) = span(w,i) + logsumexp_{k=1..w-1}( d[k][i] + d[w-k][i+k] )
//
// R5: all table LDS are lane-stride-1 (conflict-free). Lane = cell mod 32,
// G = ceil(ncell/32) chains per lane; warps split k 16 ways (warp-uniform k).

constexpr int SL = 256;
constexpr int NB = 128;
constexpr int NT = 512;     // 16 warps
constexpr int NW = 16;
constexpr float NEGF = -1000000000.0f;

// Rows padded in groups of 4 (row k has 256-4*(k>>2) floats).
__device__ __forceinline__ int off_row(int k) {
    int q = k >> 2, m = k & 3;
    return 1024 * q - 8 * q * (q - 1) + m * (256 - 4 * q);
}

constexpr int TAB_F  = 33280 + 32;             // off(256)=33280 + 32 slop
constexpr int OFF_I  = TAB_F;                  // int offs[257]
constexpr int SCRM_F = 33572;                  // scratch m: [256][17]
constexpr int SCRS_F = SCRM_F + 256 * 17;      // scratch s: [256][17]
constexpr int SMEM_F = SCRS_F + 256 * 17;
constexpr int SMEM_B = SMEM_F * 4;             // 169104 bytes

__device__ __forceinline__ void lse_merge(float& m, float& s, float mo, float so) {
    float t = __expf(-fabsf(m - mo));
    bool  p = (m >= mo);
    float shi = p ? s : so;
    float slo = p ? so : s;
    s = fmaf(slo, t, shi);
    m = p ? m : mo;
}
__device__ __forceinline__ void lse_leaf2(float& m, float& s, float v1, float v2) {
    float mp  = fmaxf(v1, v2);
    float sp2 = 1.0f + __expf(-fabsf(v1 - v2));
    lse_merge(m, s, mp, sp2);
}
__device__ __forceinline__ void lse_online(float& m, float& s, float v) {
    float d = v - m;
    float t = __expf(-fabsf(d));
    bool  p = (d > 0.0f);
    float a = p ? t : 1.0f;
    float b = p ? 1.0f : t;
    s = fmaf(s, a, b);
    m = p ? v : m;
}

// Main regime: warp ws handles k in {ws+1, ws+17, ...}; lane covers cells
// lane+32j, j<G. All loads lane-stride-1 -> conflict-free.
template<int G>
__device__ __forceinline__ void warp_kslice(
    const float* __restrict__ sd, const int* __restrict__ offs,
    float* __restrict__ scrm, float* __restrict__ scrs,
    int w, int ws, int lane)
{
    const int wm1 = w - 1;
    float m[G], s[G];
    #pragma unroll
    for (int j = 0; j < G; ++j) { m[j] = NEGF; s[j] = 0.f; }

    int k = ws + 1;
    for (; k + 16 <= wm1; k += 32) {
        const int l1 = offs[k]      + lane;
        const int l2 = offs[k + 16] + lane;
        const int r1 = offs[w - k]      + k + lane;
        const int r2 = offs[w - k - 16] + k + 16 + lane;
        #pragma unroll
        for (int j = 0; j < G; ++j) {
            const float v1 = sd[l1 + 32 * j] + sd[r1 + 32 * j];
            const float v2 = sd[l2 + 32 * j] + sd[r2 + 32 * j];
            lse_leaf2(m[j], s[j], v1, v2);
        }
    }
    if (k <= wm1) {
        const int l1 = offs[k] + lane;
        const int r1 = offs[w - k] + k + lane;
        #pragma unroll
        for (int j = 0; j < G; ++j)
            lse_online(m[j], s[j], sd[l1 + 32 * j] + sd[r1 + 32 * j]);
    }
    #pragma unroll
    for (int j = 0; j < G; ++j) {
        const int c = lane + 32 * j;
        scrm[c * 17 + ws] = m[j];
        scrs[c * 17 + ws] = s[j];
    }
}

__global__ __launch_bounds__(NT, 1)
void cyk_kernel(const float* __restrict__ s_span,
                const int* __restrict__ lens,
                float* __restrict__ out)
{
    extern __shared__ float sd[];
    int*   offs = (int*)(sd + OFF_I);
    float* scrm = sd + SCRM_F;
    float* scrs = sd + SCRS_F;
    const int tid  = threadIdx.x;
    const int ws   = tid >> 5;
    const int lane = tid & 31;
    const int b    = blockIdx.x;
    const float* S = s_span + (long long)b * (SL * SL);

    for (int i = tid; i < TAB_F; i += NT) sd[i] = NEGF;
    if (tid <= 256) offs[tid] = off_row(tid);
    __syncthreads();
    for (int i = tid; i < SL - 1; i += NT) sd[256 + i] = S[i * 257 + 1];
    __syncthreads();

    for (int w = 2; w < SL; ++w) {
        const int ncell = SL - w;
        const int wm1 = w - 1;

        float sp = 0.0f;
        if (tid < ncell) sp = S[tid * 257 + w];

        if (ncell > 16) {
            const int G = (ncell + 31) >> 5;
            switch (G) {
                case 1: warp_kslice<1>(sd, offs, scrm, scrs, w, ws, lane); break;
                case 2: warp_kslice<2>(sd, offs, scrm, scrs, w, ws, lane); break;
                case 3: warp_kslice<3>(sd, offs, scrm, scrs, w, ws, lane); break;
                case 4: warp_kslice<4>(sd, offs, scrm, scrs, w, ws, lane); break;
                case 5: warp_kslice<5>(sd, offs, scrm, scrs, w, ws, lane); break;
                case 6: warp_kslice<6>(sd, offs, scrm, scrs, w, ws, lane); break;
                case 7: warp_kslice<7>(sd, offs, scrm, scrs, w, ws, lane); break;
                default: warp_kslice<8>(sd, offs, scrm, scrs, w, ws, lane); break;
            }
        } else {
            // Tail regime: ncell <= 16. Lanes split into nsub k-slices of
            // cellP cells each; shuffle-merge across slices at the end.
            int lgc = 0;
            while ((1 << lgc) < ncell) ++lgc;      // cellP = 1<<lgc in [1,16]
            const int cellP = 1 << lgc;
            const int nsub  = 32 >> lgc;
            const int c     = lane & (cellP - 1);
            const int sub   = lane >> lgc;
            const int step  = 16 * nsub;
            float m = NEGF, s = 0.f;
            for (int k = 1 + ws + 16 * sub; k <= wm1; k += step) {
                const float v = sd[offs[k] + c] + sd[offs[w - k] + k + c];
                lse_online(m, s, v);
            }
            for (int o = cellP; o < 32; o <<= 1) {
                const float mo = __shfl_xor_sync(0xffffffffu, m, o);
                const float so = __shfl_xor_sync(0xffffffffu, s, o);
                lse_merge(m, s, mo, so);
            }
            if (sub == 0 && c < ncell) {
                scrm[c * 17 + ws] = m;
                scrs[c * 17 + ws] = s;
            }
        }
        __syncthreads();

        // Per-cell reduction over 16 warp partials: max-tree + independent exps.
        if (tid < ncell) {
            const int base = tid * 17;
            float mv[NW], sv[NW];
            #pragma unroll
            for (int j = 0; j < NW; ++j) {
                mv[j] = scrm[base + j];
                sv[j] = scrs[base + j];
            }
            float M = mv[0];
            #pragma unroll
            for (int j = 1; j < NW; ++j) M = fmaxf(M, mv[j]);
            float sa = 0.f, sb = 0.f;
            #pragma unroll
            for (int j = 0; j < NW; j += 2) {
                sa = fmaf(sv[j],     __expf(mv[j]     - M), sa);
                sb = fmaf(sv[j + 1], __expf(mv[j + 1] - M), sb);
            }
            sd[offs[w] + tid] = M + __logf(sa + sb) + sp;
        }
        __syncthreads();
    }

    if (tid == 0) {
        out[b] = sd[offs[lens[b]]];
    }
}

extern "C" void kernel_launch(void* const* d_in, const int* in_sizes, int n_in,
                              void* d_out, int out_size)
{
    const float* s_span = (const float*)d_in[0];
    const int* lens = (const int*)d_in[1];
    float* out = (float*)d_out;
    cudaFuncSetAttribute(cyk_kernel, cudaFuncAttributeMaxDynamicSharedMemorySize, SMEM_B);
    cyk_kernel<<<NB, NT, SMEM_B>>>(s_span, lens, out);
}

// round 13
// speedup vs baseline: 1.6066x; 1.1634x over previous
#include <cuda_runtime.h>

// CYK inside algorithm (TreeCRF partition). B=128, L=256.
// One CTA per batch; triangular DP table in smem, diagonal-major.
// I(w,i) = span(w,i) + logsumexp_{k=1..w-1}( d[k][i] + d[w-k][i+k] )
//
// R13: fixed-reference LSE. M_hat(w,i) = d[w-1][i] + d[1][i+w-1] (a genuine
// k=w-1 term, so s = sum_k exp(v_k - M_hat) >= 1 and result = M_hat + ln(s)
// is EXACT logsumexp). No online max, cross-warp merge is a plain sum.

constexpr int SL = 256;
constexpr int NB = 128;
constexpr int NT = 512;     // 16 warps
constexpr int NW = 16;
constexpr float NEGF = -1000000000.0f;
constexpr float L2E  = 1.4426950408889634f;   // log2(e)

// Rows padded in groups of 4 (row k has 256-4*(k>>2) floats).
__device__ __forceinline__ int off_row(int k) {
    int q = k >> 2, m = k & 3;
    return 1024 * q - 8 * q * (q - 1) + m * (256 - 4 * q);
}

constexpr int TAB_F  = 33280 + 32;             // off(256)=33280 + 32 slop
constexpr int OFF_I  = TAB_F;                  // int offs[257]
constexpr int SCR_F  = 33572;                  // scratch s: [256][17]
constexpr int SMEM_F = SCR_F + 256 * 17;
constexpr int SMEM_B = SMEM_F * 4;             // 151696 bytes

__device__ __forceinline__ float ex2(float x) {
    float r;
    asm("ex2.approx.f32 %0, %1;" : "=f"(r) : "f"(x));
    return r;
}

// Main regime: warp ws handles k in {ws+1, ws+17, ...}; lane covers cells
// lane+32j, j<G. All table LDS lane-stride-1 (conflict-free).
template<int G>
__device__ __forceinline__ void warp_kslice(
    const float* __restrict__ sd, const int* __restrict__ offs,
    float* __restrict__ scrs, int w, int ws, int lane)
{
    const int wm1 = w - 1;
    float bias[G], s[G];
    const int mb1 = offs[wm1] + lane;       // row w-1, cell c
    const int mb2 = 256 + wm1 + lane;       // row 1, cell c+w-1
    #pragma unroll
    for (int j = 0; j < G; ++j) {
        const float Mh = sd[mb1 + 32 * j] + sd[mb2 + 32 * j];
        bias[j] = -Mh * L2E;
        s[j] = 0.f;
    }

    int k = ws + 1;
    for (; k + 16 <= wm1; k += 32) {
        const int l1 = offs[k]      + lane;
        const int l2 = offs[k + 16] + lane;
        const int r1 = offs[w - k]      + k + lane;
        const int r2 = offs[w - k - 16] + k + 16 + lane;
        #pragma unroll
        for (int j = 0; j < G; ++j) {
            const float v1 = sd[l1 + 32 * j] + sd[r1 + 32 * j];
            const float v2 = sd[l2 + 32 * j] + sd[r2 + 32 * j];
            const float x1 = fminf(fmaf(v1, L2E, bias[j]), 60.f);
            const float x2 = fminf(fmaf(v2, L2E, bias[j]), 60.f);
            s[j] += ex2(x1) + ex2(x2);
        }
    }
    if (k <= wm1) {
        const int l1 = offs[k] + lane;
        const int r1 = offs[w - k] + k + lane;
        #pragma unroll
        for (int j = 0; j < G; ++j) {
            const float v = sd[l1 + 32 * j] + sd[r1 + 32 * j];
            const float x = fminf(fmaf(v, L2E, bias[j]), 60.f);
            s[j] += ex2(x);
        }
    }
    #pragma unroll
    for (int j = 0; j < G; ++j)
        scrs[(lane + 32 * j) * 17 + ws] = s[j];
}

__global__ __launch_bounds__(NT, 1)
void cyk_kernel(const float* __restrict__ s_span,
                const int* __restrict__ lens,
                float* __restrict__ out)
{
    extern __shared__ float sd[];
    int*   offs = (int*)(sd + OFF_I);
    float* scrs = sd + SCR_F;
    const int tid  = threadIdx.x;
    const int ws   = tid >> 5;
    const int lane = tid & 31;
    const int b    = blockIdx.x;
    const float* S = s_span + (long long)b * (SL * SL);

    for (int i = tid; i < TAB_F; i += NT) sd[i] = NEGF;
    if (tid <= 256) offs[tid] = off_row(tid);
    __syncthreads();
    for (int i = tid; i < SL - 1; i += NT) sd[256 + i] = S[i * 257 + 1];
    __syncthreads();

    for (int w = 2; w < SL; ++w) {
        const int ncell = SL - w;
        const int wm1 = w - 1;

        float sp = 0.0f;
        if (tid < ncell) sp = S[tid * 257 + w];

        if (ncell > 16) {
            const int G = (ncell + 31) >> 5;
            switch (G) {
                case 1: warp_kslice<1>(sd, offs, scrs, w, ws, lane); break;
                case 2: warp_kslice<2>(sd, offs, scrs, w, ws, lane); break;
                case 3: warp_kslice<3>(sd, offs, scrs, w, ws, lane); break;
                case 4: warp_kslice<4>(sd, offs, scrs, w, ws, lane); break;
                case 5: warp_kslice<5>(sd, offs, scrs, w, ws, lane); break;
                case 6: warp_kslice<6>(sd, offs, scrs, w, ws, lane); break;
                case 7: warp_kslice<7>(sd, offs, scrs, w, ws, lane); break;
                default: warp_kslice<8>(sd, offs, scrs, w, ws, lane); break;
            }
        } else {
            // Tail regime: ncell <= 16. Lanes split into nsub k-slices of
            // cellP cells; butterfly SUM across slices (shared M_hat).
            int lgc = 0;
            while ((1 << lgc) < ncell) ++lgc;      // cellP = 1<<lgc in [1,16]
            const int cellP = 1 << lgc;
            const int nsub  = 32 >> lgc;
            const int c     = lane & (cellP - 1);
            const int sub   = lane >> lgc;
            const int step  = 16 * nsub;
            const float Mh  = sd[offs[wm1] + c] + sd[256 + wm1 + c];
            const float bias = -Mh * L2E;
            float s = 0.f;
            for (int k = 1 + ws + 16 * sub; k <= wm1; k += step) {
                const float v = sd[offs[k] + c] + sd[offs[w - k] + k + c];
                s += ex2(fminf(fmaf(v, L2E, bias), 60.f));
            }
            for (int o = cellP; o < 32; o <<= 1)
                s += __shfl_xor_sync(0xffffffffu, s, o);
            if (sub == 0 && c < ncell)
                scrs[c * 17 + ws] = s;
        }
        __syncthreads();

        // Epilogue: plain sum of the 16 warp partials (shared M_hat), one log.
        if (tid < ncell) {
            const int base = tid * 17;
            float sa = 0.f, sb = 0.f;
            #pragma unroll
            for (int j = 0; j < NW; j += 2) {
                sa += scrs[base + j];
                sb += scrs[base + j + 1];
            }
            const float Mh = sd[offs[wm1] + tid] + sd[256 + wm1 + tid];
            sd[offs[w] + tid] = Mh + __logf(sa + sb) + sp;
        }
        __syncthreads();
    }

    if (tid == 0) {
        out[b] = sd[offs[lens[b]]];
    }
}

extern "C" void kernel_launch(void* const* d_in, const int* in_sizes, int n_in,
                              void* d_out, int out_size)
{
    const float* s_span = (const float*)d_in[0];
    const int* lens = (const int*)d_in[1];
    float* out = (float*)d_out;
    cudaFuncSetAttribute(cyk_kernel, cudaFuncAttributeMaxDynamicSharedMemorySize, SMEM_B);
    cyk_kernel<<<NB, NT, SMEM_B>>>(s_span, lens, out);
}

// round 15
// speedup vs baseline: 1.6779x; 1.0444x over previous
#include <cuda_runtime.h>

// CYK inside algorithm (TreeCRF partition). B=128, L=256.
// One CTA per batch; triangular DP table in smem, diagonal-major.
// I(w,i) = span(w,i) + logsumexp_{k=1..w-1}( d[k][i] + d[w-k][i+k] )
//
// R14: BASE-2 DOMAIN. Table stores T = I*log2(e). Fixed-reference LSE:
// Mh2(w,i) = T[w-1][i] + T[1][i+w-1] (genuine k=w-1 term). Per pair only
// x = Tl + Tr - Mh2; s += 2^x. No FFMA scale, no clamp (garbage-lane inf is
// confined to never-read scratch slots; no NaN paths). Result:
// T(w,i) = Mh2 + lg2(s) + span*L2E.  Final out = T * ln(2).

constexpr int SL = 256;
constexpr int NB = 128;
constexpr int NT = 512;     // 16 warps
constexpr int NW = 16;
constexpr float NEGF  = -1000000000.0f;   // already in base-2 domain
constexpr float L2E   = 1.4426950408889634f;
constexpr float LN2   = 0.6931471805599453f;

// Rows padded in groups of 4 (row k has 256-4*(k>>2) floats).
__device__ __forceinline__ int off_row(int k) {
    int q = k >> 2, m = k & 3;
    return 1024 * q - 8 * q * (q - 1) + m * (256 - 4 * q);
}

constexpr int TAB_F  = 33280 + 32;             // off(256)=33280 + 32 slop
constexpr int OFF_I  = TAB_F;                  // int offs[257]
constexpr int SCR_F  = 33572;                  // scratch s: [256][17]
constexpr int SMEM_F = SCR_F + 256 * 17;
constexpr int SMEM_B = SMEM_F * 4;             // 151696 bytes

__device__ __forceinline__ float ex2(float x) {
    float r;
    asm("ex2.approx.f32 %0, %1;" : "=f"(r) : "f"(x));
    return r;
}
__device__ __forceinline__ float lg2(float x) {
    float r;
    asm("lg2.approx.f32 %0, %1;" : "=f"(r) : "f"(x));
    return r;
}

// Main regime: warp ws handles k in {ws+1, ws+17, ...}; lane covers cells
// lane+32j, j<G. All table LDS lane-stride-1 (conflict-free).
template<int G>
__device__ __forceinline__ void warp_kslice(
    const float* __restrict__ sd, const int* __restrict__ offs,
    float* __restrict__ scrs, int w, int ws, int lane)
{
    const int wm1 = w - 1;
    float bias[G], s[G];
    const int mb1 = offs[wm1] + lane;       // row w-1, cell c   (base-2 scaled)
    const int mb2 = 256 + wm1 + lane;       // row 1, cell c+w-1 (base-2 scaled)
    #pragma unroll
    for (int j = 0; j < G; ++j) {
        bias[j] = -(sd[mb1 + 32 * j] + sd[mb2 + 32 * j]);
        s[j] = 0.f;
    }

    int k = ws + 1;
    for (; k + 16 <= wm1; k += 32) {
        const int l1 = offs[k]      + lane;
        const int l2 = offs[k + 16] + lane;
        const int r1 = offs[w - k]      + k + lane;
        const int r2 = offs[w - k - 16] + k + 16 + lane;
        #pragma unroll
        for (int j = 0; j < G; ++j) {
            const float x1 = (sd[l1 + 32 * j] + sd[r1 + 32 * j]) + bias[j];
            const float x2 = (sd[l2 + 32 * j] + sd[r2 + 32 * j]) + bias[j];
            s[j] += ex2(x1) + ex2(x2);
        }
    }
    if (k <= wm1) {
        const int l1 = offs[k] + lane;
        const int r1 = offs[w - k] + k + lane;
        #pragma unroll
        for (int j = 0; j < G; ++j) {
            const float x = (sd[l1 + 32 * j] + sd[r1 + 32 * j]) + bias[j];
            s[j] += ex2(x);
        }
    }
    #pragma unroll
    for (int j = 0; j < G; ++j)
        scrs[(lane + 32 * j) * 17 + ws] = s[j];
}

__global__ __launch_bounds__(NT, 1)
void cyk_kernel(const float* __restrict__ s_span,
                const int* __restrict__ lens,
                float* __restrict__ out)
{
    extern __shared__ float sd[];
    int*   offs = (int*)(sd + OFF_I);
    float* scrs = sd + SCR_F;
    const int tid  = threadIdx.x;
    const int ws   = tid >> 5;
    const int lane = tid & 31;
    const int b    = blockIdx.x;
    const float* S = s_span + (long long)b * (SL * SL);

    for (int i = tid; i < TAB_F; i += NT) sd[i] = NEGF;
    if (tid <= 256) offs[tid] = off_row(tid);
    __syncthreads();
    // row w=1, pre-scaled to base-2 domain
    for (int i = tid; i < SL - 1; i += NT) sd[256 + i] = S[i * 257 + 1] * L2E;
    __syncthreads();

    for (int w = 2; w < SL; ++w) {
        const int ncell = SL - w;
        const int wm1 = w - 1;

        float sp = 0.0f;
        if (tid < ncell) sp = S[tid * 257 + w];

        if (ncell > 16) {
            const int G = (ncell + 31) >> 5;
            switch (G) {
                case 1: warp_kslice<1>(sd, offs, scrs, w, ws, lane); break;
                case 2: warp_kslice<2>(sd, offs, scrs, w, ws, lane); break;
                case 3: warp_kslice<3>(sd, offs, scrs, w, ws, lane); break;
                case 4: warp_kslice<4>(sd, offs, scrs, w, ws, lane); break;
                case 5: warp_kslice<5>(sd, offs, scrs, w, ws, lane); break;
                case 6: warp_kslice<6>(sd, offs, scrs, w, ws, lane); break;
                case 7: warp_kslice<7>(sd, offs, scrs, w, ws, lane); break;
                default: warp_kslice<8>(sd, offs, scrs, w, ws, lane); break;
            }
        } else {
            // Tail regime: ncell <= 16. Lanes split into nsub k-slices of
            // cellP cells; butterfly SUM across slices (shared reference).
            int lgc = 0;
            while ((1 << lgc) < ncell) ++lgc;      // cellP = 1<<lgc in [1,16]
            const int cellP = 1 << lgc;
            const int nsub  = 32 >> lgc;
            const int c     = lane & (cellP - 1);
            const int sub   = lane >> lgc;
            const int step  = 16 * nsub;
            const float bias = -(sd[offs[wm1] + c] + sd[256 + wm1 + c]);
            float s = 0.f;
            for (int k = 1 + ws + 16 * sub; k <= wm1; k += step) {
                const float x = (sd[offs[k] + c] + sd[offs[w - k] + k + c]) + bias;
                s += ex2(x);
            }
            for (int o = cellP; o < 32; o <<= 1)
                s += __shfl_xor_sync(0xffffffffu, s, o);
            if (sub == 0 && c < ncell)
                scrs[c * 17 + ws] = s;
        }
        __syncthreads();

        // Epilogue: plain sum of 16 warp partials (shared reference), one lg2.
        if (tid < ncell) {
            const int base = tid * 17;
            float sa = 0.f, sb = 0.f;
            #pragma unroll
            for (int j = 0; j < NW; j += 2) {
                sa += scrs[base + j];
                sb += scrs[base + j + 1];
            }
            const float Mh2 = sd[offs[wm1] + tid] + sd[256 + wm1 + tid];
            sd[offs[w] + tid] = Mh2 + lg2(sa + sb) + sp * L2E;
        }
        __syncthreads();
    }

    if (tid == 0) {
        out[b] = sd[offs[lens[b]]] * LN2;   // back to natural log
    }
}

extern "C" void kernel_launch(void* const* d_in, const int* in_sizes, int n_in,
                              void* d_out, int out_size)
{
    const float* s_span = (const float*)d_in[0];
    const int* lens = (const int*)d_in[1];
    float* out = (float*)d_out;
    cudaFuncSetAttribute(cyk_kernel, cudaFuncAttributeMaxDynamicSharedMemorySize, SMEM_B);
    cyk_kernel<<<NB, NT, SMEM_B>>>(s_span, lens, out);
}